// round 8
// baseline (speedup 1.0000x reference)
#include <cuda_runtime.h>
#include <cuda_bf16.h>
#include <math.h>
#include <stdint.h>

// Problem constants
#define BB 2
#define SS 2048
#define EE 1024
#define HH 16
#define DD 64
#define MM (BB * SS)   // 4096 rows for projection GEMMs

// ---------------- scratch (device globals; no allocations allowed) ----------
__device__ float g_qp[BB * SS * EE];   // Q projected, [B,S,E]
__device__ float g_kp[BB * SS * EE];   // K projected
__device__ float g_vp[BB * SS * EE];   // V projected
__device__ float g_at[BB * SS * EE];   // attention output (concat), [B,S,E]

// ======================= helpers ============================================
__device__ __forceinline__ uint32_t smem_u32(const void* p) {
    uint32_t a;
    asm("{ .reg .u64 t; cvta.to.shared.u64 t, %1; cvt.u32.u64 %0, t; }"
        : "=r"(a) : "l"(p));
    return a;
}
__device__ __forceinline__ void cp16(uint32_t dst, const void* src) {
    asm volatile("cp.async.cg.shared.global [%0], [%1], 16;" :: "r"(dst), "l"(src));
}
#define CP_COMMIT() asm volatile("cp.async.commit_group;" ::: "memory")
#define CP_WAIT0()  asm volatile("cp.async.wait_group 0;" ::: "memory")
#define CP_WAIT1()  asm volatile("cp.async.wait_group 1;" ::: "memory")

__device__ __forceinline__ uint32_t f2tf(float x) {
    uint32_t r;
    asm("cvt.rna.tf32.f32 %0, %1;" : "=r"(r) : "f"(x));
    return r;
}
__device__ __forceinline__ void tf32_split(float x, uint32_t& hi, uint32_t& lo) {
    hi = f2tf(x);
    lo = f2tf(x - __uint_as_float(hi));
}
__device__ __forceinline__ uint32_t fu(float x) { return __float_as_uint(x); }

__device__ __forceinline__ void mma_tf32(float* d, const uint32_t* a, const uint32_t* b) {
    asm volatile(
        "mma.sync.aligned.m16n8k8.row.col.f32.tf32.tf32.f32 "
        "{%0,%1,%2,%3}, {%4,%5,%6,%7}, {%8,%9}, {%0,%1,%2,%3};"
        : "+f"(d[0]), "+f"(d[1]), "+f"(d[2]), "+f"(d[3])
        : "r"(a[0]), "r"(a[1]), "r"(a[2]), "r"(a[3]), "r"(b[0]), "r"(b[1]));
}

// ======================= tf32 mma GEMM v2 (pre-split hi/lo, float2 packed) ==
// C[M,N=1024] = A[M,K=1024] @ W[K,N] + bias.  128x128 tile, K-chunk 32,
// 256 threads = 8 warps (2M x 4N), 3xTF32. Raw tiles via cp.async double
// buffer; a split pass writes interleaved {hi,lo} float2 smem; mainloop is
// pure LDS.64 + HMMA.
#define GSA 36    // A stride: raw in floats, packed in float2
#define GSB 132   // B stride
#define RAWA_F (128 * GSA)              // 4608 floats
#define RAWB_F (32 * GSB)               // 4224 floats
#define OFF_RAW1 (RAWA_F + RAWB_F)      // 8832
#define OFF_AHL (2 * OFF_RAW1)          // 17664 (floats) -> float2 region
#define OFF_BHL (OFF_AHL + 128 * GSA * 2)   // 26880
#define GEMM2_F (OFF_BHL + 32 * GSB * 2)    // 35328 floats
#define GEMM2_B (GEMM2_F * 4)               // 141312 bytes

__device__ __forceinline__ void gemm_body(const float* __restrict__ A,
                                          const float* __restrict__ W,
                                          const float* __restrict__ bias,
                                          float* __restrict__ C)
{
    extern __shared__ float smem[];
    const uint32_t sb0 = smem_u32(smem);
    float2* Ahl = (float2*)(smem + OFF_AHL);
    float2* Bhl = (float2*)(smem + OFF_BHL);

    const int tid = threadIdx.x;
    const int lane = tid & 31;
    const int wid = tid >> 5;
    const int warpM = wid >> 2;
    const int warpN = wid & 3;
    const int bm = blockIdx.y * 128;
    const int bn = blockIdx.x * 128;
    const int lg = lane >> 2;
    const int lt = lane & 3;

    float acc[4][4][4];
#pragma unroll
    for (int mi = 0; mi < 4; mi++)
#pragma unroll
        for (int ni = 0; ni < 4; ni++)
#pragma unroll
            for (int r = 0; r < 4; r++) acc[mi][ni][r] = 0.0f;

    auto load_raw = [&](int buf, int it) {
        const float* Ab = A + (size_t)bm * EE + it * 32;
        const float* Wb = W + (size_t)(it * 32) * EE + bn;
        const uint32_t sa = sb0 + (uint32_t)(buf ? OFF_RAW1 : 0) * 4;
        const uint32_t sw = sa + RAWA_F * 4;
#pragma unroll
        for (int i = 0; i < 4; i++) {
            int cid = tid + i * 256;
            int row = cid >> 3, c4 = (cid & 7) * 4;
            cp16(sa + (uint32_t)(row * GSA + c4) * 4, Ab + (size_t)row * EE + c4);
        }
#pragma unroll
        for (int i = 0; i < 4; i++) {
            int cid = tid + i * 256;
            int kk = cid >> 5, c4 = (cid & 31) * 4;
            cp16(sw + (uint32_t)(kk * GSB + c4) * 4, Wb + (size_t)kk * EE + c4);
        }
    };

    load_raw(0, 0); CP_COMMIT();
    load_raw(1, 1); CP_COMMIT();

    for (int it = 0; it < 32; it++) {
        if (it == 31) { CP_WAIT0(); } else { CP_WAIT1(); }
        __syncthreads();   // raw[it&1] ready; prior compute done with hl bufs

        // split pass: each element split exactly once -> interleaved {hi,lo}
        const float* rA = smem + (it & 1 ? OFF_RAW1 : 0);
        const float* rB = rA + RAWA_F;
#pragma unroll
        for (int i = 0; i < 4; i++) {
            int f4 = tid + i * 256;            // A: 1024 float4
            int row = f4 >> 3, c = (f4 & 7) * 4;
            float4 v = *(const float4*)&rA[row * GSA + c];
            uint32_t h0, h1, h2, h3, l0, l1, l2, l3;
            tf32_split(v.x, h0, l0); tf32_split(v.y, h1, l1);
            tf32_split(v.z, h2, l2); tf32_split(v.w, h3, l3);
            const int base = row * GSA + c;    // float2 index
            *(uint4*)&Ahl[base]     = make_uint4(h0, l0, h1, l1);
            *(uint4*)&Ahl[base + 2] = make_uint4(h2, l2, h3, l3);
        }
#pragma unroll
        for (int i = 0; i < 4; i++) {
            int f4 = tid + i * 256;            // B: 1024 float4
            int row = f4 >> 5, c = (f4 & 31) * 4;
            float4 v = *(const float4*)&rB[row * GSB + c];
            uint32_t h0, h1, h2, h3, l0, l1, l2, l3;
            tf32_split(v.x, h0, l0); tf32_split(v.y, h1, l1);
            tf32_split(v.z, h2, l2); tf32_split(v.w, h3, l3);
            const int base = row * GSB + c;
            *(uint4*)&Bhl[base]     = make_uint4(h0, l0, h1, l1);
            *(uint4*)&Bhl[base + 2] = make_uint4(h2, l2, h3, l3);
        }
        __syncthreads();   // hl bufs ready; raw[it&1] free for reuse
        if (it + 2 < 32) { load_raw(it & 1, it + 2); CP_COMMIT(); }

        // mainloop: pure LDS.64 + HMMA
#pragma unroll
        for (int ks = 0; ks < 4; ks++) {
            const int kb = ks * 8;
            const int kk = kb + lt;
            uint32_t ah[4][4], al[4][4];
#pragma unroll
            for (int mi = 0; mi < 4; mi++) {
                const int r0m = warpM * 64 + mi * 16 + lg;
                float2 a0 = Ahl[r0m * GSA + kk];
                float2 a1 = Ahl[(r0m + 8) * GSA + kk];
                float2 a2 = Ahl[r0m * GSA + kk + 4];
                float2 a3 = Ahl[(r0m + 8) * GSA + kk + 4];
                ah[mi][0] = fu(a0.x); ah[mi][1] = fu(a1.x);
                ah[mi][2] = fu(a2.x); ah[mi][3] = fu(a3.x);
                al[mi][0] = fu(a0.y); al[mi][1] = fu(a1.y);
                al[mi][2] = fu(a2.y); al[mi][3] = fu(a3.y);
            }
            uint32_t bh[4][2], bl[4][2];
#pragma unroll
            for (int ni = 0; ni < 4; ni++) {
                const int nn = warpN * 32 + ni * 8 + lg;
                float2 b0 = Bhl[kk * GSB + nn];
                float2 b1 = Bhl[(kk + 4) * GSB + nn];
                bh[ni][0] = fu(b0.x); bh[ni][1] = fu(b1.x);
                bl[ni][0] = fu(b0.y); bl[ni][1] = fu(b1.y);
            }
#pragma unroll
            for (int mi = 0; mi < 4; mi++)
#pragma unroll
                for (int ni = 0; ni < 4; ni++) {
                    mma_tf32(acc[mi][ni], ah[mi], bh[ni]);
                    mma_tf32(acc[mi][ni], al[mi], bh[ni]);
                    mma_tf32(acc[mi][ni], ah[mi], bl[ni]);
                }
        }
    }

#pragma unroll
    for (int mi = 0; mi < 4; mi++) {
        const int row0 = bm + warpM * 64 + mi * 16 + lg;
#pragma unroll
        for (int ni = 0; ni < 4; ni++) {
            const int col = bn + warpN * 32 + ni * 8 + lt * 2;
            const float b0 = bias[col], b1 = bias[col + 1];
            float2 v0 = make_float2(acc[mi][ni][0] + b0, acc[mi][ni][1] + b1);
            float2 v1 = make_float2(acc[mi][ni][2] + b0, acc[mi][ni][3] + b1);
            *(float2*)&C[(size_t)row0 * EE + col] = v0;
            *(float2*)&C[(size_t)(row0 + 8) * EE + col] = v1;
        }
    }
}

// fused QKV: blockIdx.z selects which projection this CTA computes
__global__ __launch_bounds__(256, 1)
void gemm_qkv(const float* __restrict__ q, const float* __restrict__ k,
              const float* __restrict__ v,
              const float* __restrict__ Wq, const float* __restrict__ Wk,
              const float* __restrict__ Wv,
              const float* __restrict__ bq, const float* __restrict__ bk,
              const float* __restrict__ bv,
              float* __restrict__ qp, float* __restrict__ kp,
              float* __restrict__ vp)
{
    const int z = blockIdx.z;
    const float* A = (z == 0) ? q : (z == 1) ? k : v;
    const float* W = (z == 0) ? Wq : (z == 1) ? Wk : Wv;
    const float* bias = (z == 0) ? bq : (z == 1) ? bk : bv;
    float* C = (z == 0) ? qp : (z == 1) ? kp : vp;
    gemm_body(A, W, bias, C);
}

__global__ __launch_bounds__(256, 1)
void gemm_one(const float* __restrict__ A, const float* __restrict__ W,
              const float* __restrict__ bias, float* __restrict__ C)
{
    gemm_body(A, W, bias, C);
}

// ================= Flash attention (causal), float2-packed hi/lo ============
// FQ=128 q rows/CTA, FK=64 keys/iter, 8 warps; warp w owns q-rows
// [w*16,w*16+16) x all 64 cols. Q split once to regs; K/V/P stored as
// interleaved {hi,lo} float2 so every fragment LDS.64 feeds both mma terms.
#define FQ 128
#define FK 64
#define QR_STR 68    // raw Q floats
#define F2_STR 68    // float2 stride for P/K/V
#define OFF_PHL 8704                       // floats
#define OFF_KHL (OFF_PHL + FQ * F2_STR * 2)   // 8704+17408=26112
#define OFF_VHL (OFF_KHL + FK * F2_STR * 2)   // 26112+8704=34816
#define FLASH4_F (OFF_VHL + FK * F2_STR * 2)  // 43520 floats
#define FLASH4_B (FLASH4_F * 4)               // 174080 bytes

__global__ __launch_bounds__(256, 1)
void flash_mma_kernel(const float* __restrict__ Qp,
                      const float* __restrict__ Kp,
                      const float* __restrict__ Vp,
                      float* __restrict__ Out)
{
    extern __shared__ float sf[];
    float* Qr = sf;
    float2* Phl = (float2*)(sf + OFF_PHL);
    float2* Khl = (float2*)(sf + OFF_KHL);
    float2* Vhl = (float2*)(sf + OFF_VHL);

    const int tid = threadIdx.x;
    const int lane = tid & 31;
    const int w = tid >> 5;
    const int lg = lane >> 2;
    const int lt = lane & 3;
    const int qt = (gridDim.x - 1) - blockIdx.x;   // big CTAs first
    const int h = blockIdx.y;
    const int b = blockIdx.z;
    const int qbase = qt * FQ;
    const size_t head = (size_t)h * DD;

    // stage raw Q (pre-scaled by 1/sqrt(D)=0.125)
    for (int i = tid; i < FQ * 16; i += 256) {
        int row = i >> 4, c4 = (i & 15) * 4;
        float4 q4 = *(const float4*)&Qp[((size_t)(b * SS + qbase + row)) * EE + head + c4];
        q4.x *= 0.125f; q4.y *= 0.125f; q4.z *= 0.125f; q4.w *= 0.125f;
        *(float4*)&Qr[row * QR_STR + c4] = q4;
    }
    __syncthreads();

    const int r0 = w * 16 + lg;
    uint32_t qh[8][4], ql[8][4];
#pragma unroll
    for (int ks = 0; ks < 8; ks++) {
        const int kk = ks * 8 + lt;
        tf32_split(Qr[r0 * QR_STR + kk],           qh[ks][0], ql[ks][0]);
        tf32_split(Qr[(r0 + 8) * QR_STR + kk],     qh[ks][1], ql[ks][1]);
        tf32_split(Qr[r0 * QR_STR + kk + 4],       qh[ks][2], ql[ks][2]);
        tf32_split(Qr[(r0 + 8) * QR_STR + kk + 4], qh[ks][3], ql[ks][3]);
    }

    float oacc[8][4];
#pragma unroll
    for (int ni = 0; ni < 8; ni++)
#pragma unroll
        for (int r = 0; r < 4; r++) oacc[ni][r] = 0.0f;
    float m0 = -1e30f, m1 = -1e30f, l0 = 0.0f, l1 = 0.0f;

    const int nkt = (qbase + FQ) / FK;

    for (int kt = 0; kt < nkt; kt++) {
        const int kbase = kt * FK;
        __syncthreads();
        // load K,V; split each element once; store interleaved {hi,lo}
        for (int i = tid; i < FK * 16; i += 256) {
            int row = i >> 4, c4 = (i & 15) * 4;
            const size_t g = ((size_t)(b * SS + kbase + row)) * EE + head + c4;
            float4 k4 = *(const float4*)&Kp[g];
            float4 v4 = *(const float4*)&Vp[g];
            uint32_t h0, h1, h2, h3, lo0, lo1, lo2, lo3;
            const int base = row * F2_STR + c4;
            tf32_split(k4.x, h0, lo0); tf32_split(k4.y, h1, lo1);
            tf32_split(k4.z, h2, lo2); tf32_split(k4.w, h3, lo3);
            *(uint4*)&Khl[base]     = make_uint4(h0, lo0, h1, lo1);
            *(uint4*)&Khl[base + 2] = make_uint4(h2, lo2, h3, lo3);
            tf32_split(v4.x, h0, lo0); tf32_split(v4.y, h1, lo1);
            tf32_split(v4.z, h2, lo2); tf32_split(v4.w, h3, lo3);
            *(uint4*)&Vhl[base]     = make_uint4(h0, lo0, h1, lo1);
            *(uint4*)&Vhl[base + 2] = make_uint4(h2, lo2, h3, lo3);
        }
        __syncthreads();

        // ---- S = Q @ K^T
        float sacc[8][4];
#pragma unroll
        for (int ni = 0; ni < 8; ni++)
#pragma unroll
            for (int r = 0; r < 4; r++) sacc[ni][r] = 0.0f;

#pragma unroll
        for (int ks = 0; ks < 8; ks++) {
            const int kk = ks * 8 + lt;
#pragma unroll
            for (int ni = 0; ni < 8; ni++) {
                const int krow = ni * 8 + lg;
                float2 k0 = Khl[krow * F2_STR + kk];
                float2 k1 = Khl[krow * F2_STR + kk + 4];
                uint32_t bh[2] = {fu(k0.x), fu(k1.x)};
                uint32_t bl[2] = {fu(k0.y), fu(k1.y)};
                mma_tf32(sacc[ni], qh[ks], bh);
                mma_tf32(sacc[ni], ql[ks], bh);
                mma_tf32(sacc[ni], qh[ks], bl);
            }
        }

        // ---- causal mask (near-diagonal tiles only)
        if (kt >= 2 * qt) {
            const int grow0 = qbase + r0;
#pragma unroll
            for (int ni = 0; ni < 8; ni++) {
                const int c0 = kbase + ni * 8 + lt * 2;
                if (c0 > grow0)         sacc[ni][0] = -1e30f;
                if (c0 + 1 > grow0)     sacc[ni][1] = -1e30f;
                if (c0 > grow0 + 8)     sacc[ni][2] = -1e30f;
                if (c0 + 1 > grow0 + 8) sacc[ni][3] = -1e30f;
            }
        }

        // ---- online softmax
        float rmax0 = -1e30f, rmax1 = -1e30f;
#pragma unroll
        for (int ni = 0; ni < 8; ni++) {
            rmax0 = fmaxf(rmax0, fmaxf(sacc[ni][0], sacc[ni][1]));
            rmax1 = fmaxf(rmax1, fmaxf(sacc[ni][2], sacc[ni][3]));
        }
        rmax0 = fmaxf(rmax0, __shfl_xor_sync(0xffffffffu, rmax0, 1));
        rmax0 = fmaxf(rmax0, __shfl_xor_sync(0xffffffffu, rmax0, 2));
        rmax1 = fmaxf(rmax1, __shfl_xor_sync(0xffffffffu, rmax1, 1));
        rmax1 = fmaxf(rmax1, __shfl_xor_sync(0xffffffffu, rmax1, 2));

        const float newm0 = fmaxf(m0, rmax0);
        const float newm1 = fmaxf(m1, rmax1);
        const float alpha0 = __expf(m0 - newm0);
        const float alpha1 = __expf(m1 - newm1);
        m0 = newm0; m1 = newm1;

        float rsum0 = 0.0f, rsum1 = 0.0f;
#pragma unroll
        for (int ni = 0; ni < 8; ni++) {
            sacc[ni][0] = __expf(sacc[ni][0] - m0);
            sacc[ni][1] = __expf(sacc[ni][1] - m0);
            sacc[ni][2] = __expf(sacc[ni][2] - m1);
            sacc[ni][3] = __expf(sacc[ni][3] - m1);
            rsum0 += sacc[ni][0] + sacc[ni][1];
            rsum1 += sacc[ni][2] + sacc[ni][3];
        }
        rsum0 += __shfl_xor_sync(0xffffffffu, rsum0, 1);
        rsum0 += __shfl_xor_sync(0xffffffffu, rsum0, 2);
        rsum1 += __shfl_xor_sync(0xffffffffu, rsum1, 1);
        rsum1 += __shfl_xor_sync(0xffffffffu, rsum1, 2);
        l0 = l0 * alpha0 + rsum0;
        l1 = l1 * alpha1 + rsum1;

        // rescale O; split P once; store interleaved {hi,lo}
#pragma unroll
        for (int ni = 0; ni < 8; ni++) {
            oacc[ni][0] *= alpha0;
            oacc[ni][1] *= alpha0;
            oacc[ni][2] *= alpha1;
            oacc[ni][3] *= alpha1;
            uint32_t h0, h1, lo0, lo1;
            const int c = ni * 8 + lt * 2;
            tf32_split(sacc[ni][0], h0, lo0);
            tf32_split(sacc[ni][1], h1, lo1);
            *(uint4*)&Phl[r0 * F2_STR + c] = make_uint4(h0, lo0, h1, lo1);
            tf32_split(sacc[ni][2], h0, lo0);
            tf32_split(sacc[ni][3], h1, lo1);
            *(uint4*)&Phl[(r0 + 8) * F2_STR + c] = make_uint4(h0, lo0, h1, lo1);
        }
        __syncwarp();   // warp reads only its own P rows

        // ---- O += P @ V
#pragma unroll
        for (int ks = 0; ks < 8; ks++) {
            const int kk = ks * 8 + lt;
            float2 p0 = Phl[r0 * F2_STR + kk];
            float2 p1 = Phl[(r0 + 8) * F2_STR + kk];
            float2 p2 = Phl[r0 * F2_STR + kk + 4];
            float2 p3 = Phl[(r0 + 8) * F2_STR + kk + 4];
            uint32_t ph[4] = {fu(p0.x), fu(p1.x), fu(p2.x), fu(p3.x)};
            uint32_t pl[4] = {fu(p0.y), fu(p1.y), fu(p2.y), fu(p3.y)};
#pragma unroll
            for (int ni = 0; ni < 8; ni++) {
                const int c = ni * 8 + lg;
                float2 v0 = Vhl[kk * F2_STR + c];
                float2 v1 = Vhl[(kk + 4) * F2_STR + c];
                uint32_t bh[2] = {fu(v0.x), fu(v1.x)};
                uint32_t bl[2] = {fu(v0.y), fu(v1.y)};
                mma_tf32(oacc[ni], ph, bh);
                mma_tf32(oacc[ni], pl, bh);
                mma_tf32(oacc[ni], ph, bl);
            }
        }
    }

    // ---- epilogue
    const float inv0 = 1.0f / l0;
    const float inv1 = 1.0f / l1;
    const int grow = qbase + r0;
#pragma unroll
    for (int ni = 0; ni < 8; ni++) {
        const size_t col = head + ni * 8 + lt * 2;
        *(float2*)&Out[((size_t)(b * SS + grow)) * EE + col] =
            make_float2(oacc[ni][0] * inv0, oacc[ni][1] * inv0);
        *(float2*)&Out[((size_t)(b * SS + grow + 8)) * EE + col] =
            make_float2(oacc[ni][2] * inv1, oacc[ni][3] * inv1);
    }
}

// ---------------- launch ----------------------------------------------------
extern "C" void kernel_launch(void* const* d_in, const int* in_sizes, int n_in,
                              void* d_out, int out_size)
{
    const float* q  = (const float*)d_in[0];
    const float* k  = (const float*)d_in[1];
    const float* v  = (const float*)d_in[2];
    const float* Wq = (const float*)d_in[3];
    const float* bq = (const float*)d_in[4];
    const float* Wk = (const float*)d_in[5];
    const float* bk = (const float*)d_in[6];
    const float* Wv = (const float*)d_in[7];
    const float* bv = (const float*)d_in[8];
    const float* Wo = (const float*)d_in[9];
    const float* bo = (const float*)d_in[10];
    float* out = (float*)d_out;

    float* qp; cudaGetSymbolAddress((void**)&qp, g_qp);
    float* kp; cudaGetSymbolAddress((void**)&kp, g_kp);
    float* vp; cudaGetSymbolAddress((void**)&vp, g_vp);
    float* at; cudaGetSymbolAddress((void**)&at, g_at);

    cudaFuncSetAttribute(gemm_qkv,
                         cudaFuncAttributeMaxDynamicSharedMemorySize, GEMM2_B);
    cudaFuncSetAttribute(gemm_one,
                         cudaFuncAttributeMaxDynamicSharedMemorySize, GEMM2_B);
    cudaFuncSetAttribute(flash_mma_kernel,
                         cudaFuncAttributeMaxDynamicSharedMemorySize, FLASH4_B);

    dim3 qkv_grid(EE / 128, MM / 128, 3);   // (8, 32, 3)
    gemm_qkv<<<qkv_grid, 256, GEMM2_B>>>(q, k, v, Wq, Wk, Wv, bq, bk, bv,
                                         qp, kp, vp);

    dim3 fa_grid(SS / FQ, HH, BB);          // (16, 16, 2)
    flash_mma_kernel<<<fa_grid, 256, FLASH4_B>>>(qp, kp, vp, at);

    dim3 ggrid(EE / 128, MM / 128);         // (8, 32)
    gemm_one<<<ggrid, 256, GEMM2_B>>>(at, Wo, bo, out);
}

// round 10
// speedup vs baseline: 1.7420x; 1.7420x over previous
#include <cuda_runtime.h>
#include <cuda_bf16.h>
#include <math.h>
#include <stdint.h>

// Problem constants
#define BB 2
#define SS 2048
#define EE 1024
#define HH 16
#define DD 64
#define MM (BB * SS)   // 4096 rows for projection GEMMs

// ---------------- scratch (device globals; no allocations allowed) ----------
__device__ float g_qp[BB * SS * EE];   // Q projected, [B,S,E]
__device__ float g_kp[BB * SS * EE];   // K projected
__device__ float g_vp[BB * SS * EE];   // V projected
__device__ float g_at[BB * SS * EE];   // attention output (concat), [B,S,E]

// ======================= helpers ============================================
__device__ __forceinline__ uint32_t smem_u32(const void* p) {
    uint32_t a;
    asm("{ .reg .u64 t; cvta.to.shared.u64 t, %1; cvt.u32.u64 %0, t; }"
        : "=r"(a) : "l"(p));
    return a;
}
__device__ __forceinline__ void cp16(uint32_t dst, const void* src) {
    asm volatile("cp.async.cg.shared.global [%0], [%1], 16;" :: "r"(dst), "l"(src));
}
#define CP_COMMIT() asm volatile("cp.async.commit_group;" ::: "memory")
#define CP_WAIT0()  asm volatile("cp.async.wait_group 0;" ::: "memory")
#define CP_WAIT1()  asm volatile("cp.async.wait_group 1;" ::: "memory")

__device__ __forceinline__ uint32_t f2tf(float x) {
    uint32_t r;
    asm("cvt.rna.tf32.f32 %0, %1;" : "=r"(r) : "f"(x));
    return r;
}
__device__ __forceinline__ void tf32_split(float x, uint32_t& hi, uint32_t& lo) {
    hi = f2tf(x);
    lo = f2tf(x - __uint_as_float(hi));
}
__device__ __forceinline__ uint32_t fu(float x) { return __float_as_uint(x); }

__device__ __forceinline__ void mma_tf32(float* d, const uint32_t* a, const uint32_t* b) {
    asm volatile(
        "mma.sync.aligned.m16n8k8.row.col.f32.tf32.tf32.f32 "
        "{%0,%1,%2,%3}, {%4,%5,%6,%7}, {%8,%9}, {%0,%1,%2,%3};"
        : "+f"(d[0]), "+f"(d[1]), "+f"(d[2]), "+f"(d[3])
        : "r"(a[0]), "r"(a[1]), "r"(a[2]), "r"(a[3]), "r"(b[0]), "r"(b[1]));
}

// ======================= tf32 mma.sync GEMM (R7-proven version) =============
// C[M,N=1024] = A[M,K=1024] @ W[K,N] + bias.  3xTF32, splits inline in the
// mainloop (dual-issue against HMMA). 128x128 tile, K-chunk 32, 256 threads.
#define SA 36
#define SB 132
#define A_BUF_F (128 * SA)
#define B_BUF_F (32 * SB)
#define GEMM_SMEM_F (2 * A_BUF_F + 2 * B_BUF_F)
#define GEMM_SMEM_B (GEMM_SMEM_F * 4)

__device__ __forceinline__ void gemm_body(const float* __restrict__ A,
                                          const float* __restrict__ W,
                                          const float* __restrict__ bias,
                                          float* __restrict__ C)
{
    extern __shared__ float smem[];
    float* As[2] = {smem, smem + A_BUF_F};
    float* Bs[2] = {smem + 2 * A_BUF_F, smem + 2 * A_BUF_F + B_BUF_F};
    const uint32_t sb0 = smem_u32(smem);

    const int tid = threadIdx.x;
    const int lane = tid & 31;
    const int wid = tid >> 5;
    const int warpM = wid >> 2;
    const int warpN = wid & 3;
    const int bm = blockIdx.y * 128;
    const int bn = blockIdx.x * 128;

    const int lg = lane >> 2;
    const int lt = lane & 3;

    float acc[4][4][4];
#pragma unroll
    for (int mi = 0; mi < 4; mi++)
#pragma unroll
        for (int ni = 0; ni < 4; ni++)
#pragma unroll
            for (int r = 0; r < 4; r++) acc[mi][ni][r] = 0.0f;

    auto load_tiles = [&](int buf, int it) {
        const float* Ab = A + (size_t)bm * EE + it * 32;
        const float* Wb = W + (size_t)(it * 32) * EE + bn;
        const uint32_t sa = sb0 + (uint32_t)((As[buf] - smem) * 4);
        const uint32_t sw = sb0 + (uint32_t)((Bs[buf] - smem) * 4);
#pragma unroll
        for (int i = 0; i < 4; i++) {
            int cid = tid + i * 256;
            int row = cid >> 3, c4 = (cid & 7) * 4;
            cp16(sa + (uint32_t)(row * SA + c4) * 4, Ab + (size_t)row * EE + c4);
        }
#pragma unroll
        for (int i = 0; i < 4; i++) {
            int cid = tid + i * 256;
            int kk = cid >> 5, c4 = (cid & 31) * 4;
            cp16(sw + (uint32_t)(kk * SB + c4) * 4, Wb + (size_t)kk * EE + c4);
        }
    };

    load_tiles(0, 0); CP_COMMIT();
    load_tiles(1, 1); CP_COMMIT();

    for (int it = 0; it < 32; it++) {
        if (it == 31) { CP_WAIT0(); } else { CP_WAIT1(); }
        __syncthreads();

        const float* A_ = As[it & 1];
        const float* B_ = Bs[it & 1];

#pragma unroll
        for (int ks = 0; ks < 4; ks++) {
            const int kb = ks * 8;
            uint32_t ah[4][4], al[4][4];
#pragma unroll
            for (int mi = 0; mi < 4; mi++) {
                const int r0 = warpM * 64 + mi * 16 + lg;
                const int kk = kb + lt;
                tf32_split(A_[r0 * SA + kk],        ah[mi][0], al[mi][0]);
                tf32_split(A_[(r0 + 8) * SA + kk],  ah[mi][1], al[mi][1]);
                tf32_split(A_[r0 * SA + kk + 4],    ah[mi][2], al[mi][2]);
                tf32_split(A_[(r0 + 8) * SA + kk + 4], ah[mi][3], al[mi][3]);
            }
            uint32_t bh[4][2], bl[4][2];
#pragma unroll
            for (int ni = 0; ni < 4; ni++) {
                const int nn = warpN * 32 + ni * 8 + lg;
                const int kk = kb + lt;
                tf32_split(B_[kk * SB + nn],       bh[ni][0], bl[ni][0]);
                tf32_split(B_[(kk + 4) * SB + nn], bh[ni][1], bl[ni][1]);
            }
#pragma unroll
            for (int mi = 0; mi < 4; mi++)
#pragma unroll
                for (int ni = 0; ni < 4; ni++) {
                    mma_tf32(acc[mi][ni], ah[mi], bh[ni]);
                    mma_tf32(acc[mi][ni], al[mi], bh[ni]);
                    mma_tf32(acc[mi][ni], ah[mi], bl[ni]);
                }
        }
        __syncthreads();
        if (it + 2 < 32) { load_tiles(it & 1, it + 2); CP_COMMIT(); }
    }

#pragma unroll
    for (int mi = 0; mi < 4; mi++) {
        const int row0 = bm + warpM * 64 + mi * 16 + lg;
#pragma unroll
        for (int ni = 0; ni < 4; ni++) {
            const int col = bn + warpN * 32 + ni * 8 + lt * 2;
            const float b0 = bias[col], b1 = bias[col + 1];
            float2 v0 = make_float2(acc[mi][ni][0] + b0, acc[mi][ni][1] + b1);
            float2 v1 = make_float2(acc[mi][ni][2] + b0, acc[mi][ni][3] + b1);
            *(float2*)&C[(size_t)row0 * EE + col] = v0;
            *(float2*)&C[(size_t)(row0 + 8) * EE + col] = v1;
        }
    }
}

// fused QKV: blockIdx.z selects which projection this CTA computes
__global__ __launch_bounds__(256, 1)
void gemm_qkv(const float* __restrict__ q, const float* __restrict__ k,
              const float* __restrict__ v,
              const float* __restrict__ Wq, const float* __restrict__ Wk,
              const float* __restrict__ Wv,
              const float* __restrict__ bq, const float* __restrict__ bk,
              const float* __restrict__ bv,
              float* __restrict__ qp, float* __restrict__ kp,
              float* __restrict__ vp)
{
    const int z = blockIdx.z;
    const float* A = (z == 0) ? q : (z == 1) ? k : v;
    const float* W = (z == 0) ? Wq : (z == 1) ? Wk : Wv;
    const float* bias = (z == 0) ? bq : (z == 1) ? bk : bv;
    float* C = (z == 0) ? qp : (z == 1) ? kp : vp;
    gemm_body(A, W, bias, C);
}

__global__ __launch_bounds__(256, 1)
void gemm_one(const float* __restrict__ A, const float* __restrict__ W,
              const float* __restrict__ bias, float* __restrict__ C)
{
    gemm_body(A, W, bias, C);
}

// ================= Flash attention (causal), float2-packed hi/lo ============
// FQ=128 q rows/CTA, FK=64 keys/iter, 8 warps; warp w owns q-rows
// [w*16,w*16+16) x all 64 cols. Q split once to regs; K/V/P stored as
// interleaved {hi,lo} float2 so every fragment LDS.64 feeds both mma terms.
#define FQ 128
#define FK 64
#define QR_STR 68    // raw Q floats
#define F2_STR 68    // float2 stride for P/K/V
#define OFF_PHL 8704                       // floats
#define OFF_KHL (OFF_PHL + FQ * F2_STR * 2)   // 26112
#define OFF_VHL (OFF_KHL + FK * F2_STR * 2)   // 34816
#define FLASH4_F (OFF_VHL + FK * F2_STR * 2)  // 43520 floats
#define FLASH4_B (FLASH4_F * 4)               // 174080 bytes

__global__ __launch_bounds__(256, 1)
void flash_mma_kernel(const float* __restrict__ Qp,
                      const float* __restrict__ Kp,
                      const float* __restrict__ Vp,
                      float* __restrict__ Out)
{
    extern __shared__ float sf[];
    float* Qr = sf;
    float2* Phl = (float2*)(sf + OFF_PHL);
    float2* Khl = (float2*)(sf + OFF_KHL);
    float2* Vhl = (float2*)(sf + OFF_VHL);

    const int tid = threadIdx.x;
    const int lane = tid & 31;
    const int w = tid >> 5;
    const int lg = lane >> 2;
    const int lt = lane & 3;
    const int qt = (gridDim.x - 1) - blockIdx.x;   // big CTAs first
    const int h = blockIdx.y;
    const int b = blockIdx.z;
    const int qbase = qt * FQ;
    const size_t head = (size_t)h * DD;

    // stage raw Q (pre-scaled by 1/sqrt(D)=0.125)
    for (int i = tid; i < FQ * 16; i += 256) {
        int row = i >> 4, c4 = (i & 15) * 4;
        float4 q4 = *(const float4*)&Qp[((size_t)(b * SS + qbase + row)) * EE + head + c4];
        q4.x *= 0.125f; q4.y *= 0.125f; q4.z *= 0.125f; q4.w *= 0.125f;
        *(float4*)&Qr[row * QR_STR + c4] = q4;
    }
    __syncthreads();

    const int r0 = w * 16 + lg;
    uint32_t qh[8][4], ql[8][4];
#pragma unroll
    for (int ks = 0; ks < 8; ks++) {
        const int kk = ks * 8 + lt;
        tf32_split(Qr[r0 * QR_STR + kk],           qh[ks][0], ql[ks][0]);
        tf32_split(Qr[(r0 + 8) * QR_STR + kk],     qh[ks][1], ql[ks][1]);
        tf32_split(Qr[r0 * QR_STR + kk + 4],       qh[ks][2], ql[ks][2]);
        tf32_split(Qr[(r0 + 8) * QR_STR + kk + 4], qh[ks][3], ql[ks][3]);
    }

    float oacc[8][4];
#pragma unroll
    for (int ni = 0; ni < 8; ni++)
#pragma unroll
        for (int r = 0; r < 4; r++) oacc[ni][r] = 0.0f;
    float m0 = -1e30f, m1 = -1e30f, l0 = 0.0f, l1 = 0.0f;

    const int nkt = (qbase + FQ) / FK;

    for (int kt = 0; kt < nkt; kt++) {
        const int kbase = kt * FK;
        __syncthreads();
        // load K,V; split each element once; store interleaved {hi,lo}
        for (int i = tid; i < FK * 16; i += 256) {
            int row = i >> 4, c4 = (i & 15) * 4;
            const size_t g = ((size_t)(b * SS + kbase + row)) * EE + head + c4;
            float4 k4 = *(const float4*)&Kp[g];
            float4 v4 = *(const float4*)&Vp[g];
            uint32_t h0, h1, h2, h3, lo0, lo1, lo2, lo3;
            const int base = row * F2_STR + c4;
            tf32_split(k4.x, h0, lo0); tf32_split(k4.y, h1, lo1);
            tf32_split(k4.z, h2, lo2); tf32_split(k4.w, h3, lo3);
            *(uint4*)&Khl[base]     = make_uint4(h0, lo0, h1, lo1);
            *(uint4*)&Khl[base + 2] = make_uint4(h2, lo2, h3, lo3);
            tf32_split(v4.x, h0, lo0); tf32_split(v4.y, h1, lo1);
            tf32_split(v4.z, h2, lo2); tf32_split(v4.w, h3, lo3);
            *(uint4*)&Vhl[base]     = make_uint4(h0, lo0, h1, lo1);
            *(uint4*)&Vhl[base + 2] = make_uint4(h2, lo2, h3, lo3);
        }
        __syncthreads();

        // ---- S = Q @ K^T
        float sacc[8][4];
#pragma unroll
        for (int ni = 0; ni < 8; ni++)
#pragma unroll
            for (int r = 0; r < 4; r++) sacc[ni][r] = 0.0f;

#pragma unroll
        for (int ks = 0; ks < 8; ks++) {
            const int kk = ks * 8 + lt;
#pragma unroll
            for (int ni = 0; ni < 8; ni++) {
                const int krow = ni * 8 + lg;
                float2 k0 = Khl[krow * F2_STR + kk];
                float2 k1 = Khl[krow * F2_STR + kk + 4];
                uint32_t bh[2] = {fu(k0.x), fu(k1.x)};
                uint32_t bl[2] = {fu(k0.y), fu(k1.y)};
                mma_tf32(sacc[ni], qh[ks], bh);
                mma_tf32(sacc[ni], ql[ks], bh);
                mma_tf32(sacc[ni], qh[ks], bl);
            }
        }

        // ---- causal mask (near-diagonal tiles only)
        if (kt >= 2 * qt) {
            const int grow0 = qbase + r0;
#pragma unroll
            for (int ni = 0; ni < 8; ni++) {
                const int c0 = kbase + ni * 8 + lt * 2;
                if (c0 > grow0)         sacc[ni][0] = -1e30f;
                if (c0 + 1 > grow0)     sacc[ni][1] = -1e30f;
                if (c0 > grow0 + 8)     sacc[ni][2] = -1e30f;
                if (c0 + 1 > grow0 + 8) sacc[ni][3] = -1e30f;
            }
        }

        // ---- online softmax
        float rmax0 = -1e30f, rmax1 = -1e30f;
#pragma unroll
        for (int ni = 0; ni < 8; ni++) {
            rmax0 = fmaxf(rmax0, fmaxf(sacc[ni][0], sacc[ni][1]));
            rmax1 = fmaxf(rmax1, fmaxf(sacc[ni][2], sacc[ni][3]));
        }
        rmax0 = fmaxf(rmax0, __shfl_xor_sync(0xffffffffu, rmax0, 1));
        rmax0 = fmaxf(rmax0, __shfl_xor_sync(0xffffffffu, rmax0, 2));
        rmax1 = fmaxf(rmax1, __shfl_xor_sync(0xffffffffu, rmax1, 1));
        rmax1 = fmaxf(rmax1, __shfl_xor_sync(0xffffffffu, rmax1, 2));

        const float newm0 = fmaxf(m0, rmax0);
        const float newm1 = fmaxf(m1, rmax1);
        const float alpha0 = __expf(m0 - newm0);
        const float alpha1 = __expf(m1 - newm1);
        m0 = newm0; m1 = newm1;

        float rsum0 = 0.0f, rsum1 = 0.0f;
#pragma unroll
        for (int ni = 0; ni < 8; ni++) {
            sacc[ni][0] = __expf(sacc[ni][0] - m0);
            sacc[ni][1] = __expf(sacc[ni][1] - m0);
            sacc[ni][2] = __expf(sacc[ni][2] - m1);
            sacc[ni][3] = __expf(sacc[ni][3] - m1);
            rsum0 += sacc[ni][0] + sacc[ni][1];
            rsum1 += sacc[ni][2] + sacc[ni][3];
        }
        rsum0 += __shfl_xor_sync(0xffffffffu, rsum0, 1);
        rsum0 += __shfl_xor_sync(0xffffffffu, rsum0, 2);
        rsum1 += __shfl_xor_sync(0xffffffffu, rsum1, 1);
        rsum1 += __shfl_xor_sync(0xffffffffu, rsum1, 2);
        l0 = l0 * alpha0 + rsum0;
        l1 = l1 * alpha1 + rsum1;

        // rescale O; split P once; store interleaved {hi,lo}
#pragma unroll
        for (int ni = 0; ni < 8; ni++) {
            oacc[ni][0] *= alpha0;
            oacc[ni][1] *= alpha0;
            oacc[ni][2] *= alpha1;
            oacc[ni][3] *= alpha1;
            uint32_t h0, h1, lo0, lo1;
            const int c = ni * 8 + lt * 2;
            tf32_split(sacc[ni][0], h0, lo0);
            tf32_split(sacc[ni][1], h1, lo1);
            *(uint4*)&Phl[r0 * F2_STR + c] = make_uint4(h0, lo0, h1, lo1);
            tf32_split(sacc[ni][2], h0, lo0);
            tf32_split(sacc[ni][3], h1, lo1);
            *(uint4*)&Phl[(r0 + 8) * F2_STR + c] = make_uint4(h0, lo0, h1, lo1);
        }
        __syncwarp();   // warp reads only its own P rows

        // ---- O += P @ V
#pragma unroll
        for (int ks = 0; ks < 8; ks++) {
            const int kk = ks * 8 + lt;
            float2 p0 = Phl[r0 * F2_STR + kk];
            float2 p1 = Phl[(r0 + 8) * F2_STR + kk];
            float2 p2 = Phl[r0 * F2_STR + kk + 4];
            float2 p3 = Phl[(r0 + 8) * F2_STR + kk + 4];
            uint32_t ph[4] = {fu(p0.x), fu(p1.x), fu(p2.x), fu(p3.x)};
            uint32_t pl[4] = {fu(p0.y), fu(p1.y), fu(p2.y), fu(p3.y)};
#pragma unroll
            for (int ni = 0; ni < 8; ni++) {
                const int c = ni * 8 + lg;
                float2 v0 = Vhl[kk * F2_STR + c];
                float2 v1 = Vhl[(kk + 4) * F2_STR + c];
                uint32_t bh[2] = {fu(v0.x), fu(v1.x)};
                uint32_t bl[2] = {fu(v0.y), fu(v1.y)};
                mma_tf32(oacc[ni], ph, bh);
                mma_tf32(oacc[ni], pl, bh);
                mma_tf32(oacc[ni], ph, bl);
            }
        }
    }

    // ---- epilogue
    const float inv0 = 1.0f / l0;
    const float inv1 = 1.0f / l1;
    const int grow = qbase + r0;
#pragma unroll
    for (int ni = 0; ni < 8; ni++) {
        const size_t col = head + ni * 8 + lt * 2;
        *(float2*)&Out[((size_t)(b * SS + grow)) * EE + col] =
            make_float2(oacc[ni][0] * inv0, oacc[ni][1] * inv0);
        *(float2*)&Out[((size_t)(b * SS + grow + 8)) * EE + col] =
            make_float2(oacc[ni][2] * inv1, oacc[ni][3] * inv1);
    }
}

// ---------------- launch ----------------------------------------------------
extern "C" void kernel_launch(void* const* d_in, const int* in_sizes, int n_in,
                              void* d_out, int out_size)
{
    const float* q  = (const float*)d_in[0];
    const float* k  = (const float*)d_in[1];
    const float* v  = (const float*)d_in[2];
    const float* Wq = (const float*)d_in[3];
    const float* bq = (const float*)d_in[4];
    const float* Wk = (const float*)d_in[5];
    const float* bk = (const float*)d_in[6];
    const float* Wv = (const float*)d_in[7];
    const float* bv = (const float*)d_in[8];
    const float* Wo = (const float*)d_in[9];
    const float* bo = (const float*)d_in[10];
    float* out = (float*)d_out;

    float* qp; cudaGetSymbolAddress((void**)&qp, g_qp);
    float* kp; cudaGetSymbolAddress((void**)&kp, g_kp);
    float* vp; cudaGetSymbolAddress((void**)&vp, g_vp);
    float* at; cudaGetSymbolAddress((void**)&at, g_at);

    cudaFuncSetAttribute(gemm_qkv,
                         cudaFuncAttributeMaxDynamicSharedMemorySize, GEMM_SMEM_B);
    cudaFuncSetAttribute(gemm_one,
                         cudaFuncAttributeMaxDynamicSharedMemorySize, GEMM_SMEM_B);
    cudaFuncSetAttribute(flash_mma_kernel,
                         cudaFuncAttributeMaxDynamicSharedMemorySize, FLASH4_B);

    dim3 qkv_grid(EE / 128, MM / 128, 3);   // (8, 32, 3)
    gemm_qkv<<<qkv_grid, 256, GEMM_SMEM_B>>>(q, k, v, Wq, Wk, Wv, bq, bk, bv,
                                             qp, kp, vp);

    dim3 fa_grid(SS / FQ, HH, BB);          // (16, 16, 2)
    flash_mma_kernel<<<fa_grid, 256, FLASH4_B>>>(qp, kp, vp, at);

    dim3 ggrid(EE / 128, MM / 128);         // (8, 32)
    gemm_one<<<ggrid, 256, GEMM_SMEM_B>>>(at, Wo, bo, out);
}

// round 11
// speedup vs baseline: 2.9652x; 1.7022x over previous
#include <cuda_runtime.h>
#include <cuda_bf16.h>
#include <math.h>
#include <stdint.h>

// Problem constants
#define BB 2
#define SS 2048
#define EE 1024
#define HH 16
#define DD 64
#define MM (BB * SS)

// ---------------- scratch (device globals; no allocations allowed) ----------
__device__ float g_qp[BB * SS * EE];
__device__ float g_kp[BB * SS * EE];
__device__ float g_vp[BB * SS * EE];
__device__ float g_at[BB * SS * EE];

// ======================= helpers ============================================
// pack two fp32 into bf16x2: low half = x0, high half = x1
__device__ __forceinline__ uint32_t packbf(float x0, float x1) {
    uint32_t r;
    asm("cvt.rn.bf16x2.f32 %0, %1, %2;" : "=r"(r) : "f"(x1), "f"(x0));
    return r;
}
// split (x0,x1) into {hi-pair, lo-pair} bf16x2 words
__device__ __forceinline__ void bf_split2(float x0, float x1,
                                          uint32_t& h2, uint32_t& l2) {
    h2 = packbf(x0, x1);
    float h0 = __uint_as_float(h2 << 16);
    float h1 = __uint_as_float(h2 & 0xffff0000u);
    l2 = packbf(x0 - h0, x1 - h1);
}
__device__ __forceinline__ float ex2(float x) {
    float r;
    asm("ex2.approx.f32 %0, %1;" : "=f"(r) : "f"(x));
    return r;
}
__device__ __forceinline__ void mma_bf16(float* d, const uint32_t* a, const uint32_t* b) {
    asm volatile(
        "mma.sync.aligned.m16n8k16.row.col.f32.bf16.bf16.f32 "
        "{%0,%1,%2,%3}, {%4,%5,%6,%7}, {%8,%9}, {%0,%1,%2,%3};"
        : "+f"(d[0]), "+f"(d[1]), "+f"(d[2]), "+f"(d[3])
        : "r"(a[0]), "r"(a[1]), "r"(a[2]), "r"(a[3]), "r"(b[0]), "r"(b[1]));
}

// ======================= bf16 3-term split GEMM =============================
#define GA_STR 20
#define GB_STR 132
#define GA_U2 (128 * GA_STR)
#define GB_U2 (16 * GB_STR)
#define GEMM3_B ((GA_U2 + GB_U2) * 8)   // 37376 bytes

__device__ __forceinline__ void gemm_body(const float* __restrict__ A,
                                          const float* __restrict__ W,
                                          const float* __restrict__ bias,
                                          float* __restrict__ C)
{
    extern __shared__ uint2 su[];
    uint2* Ah = su;
    uint2* Bh = su + GA_U2;

    const int tid = threadIdx.x;
    const int lane = tid & 31;
    const int wid = tid >> 5;
    const int warpM = wid >> 2;
    const int warpN = wid & 3;
    const int bm = blockIdx.y * 128;
    const int bn = blockIdx.x * 128;
    const int lg = lane >> 2;
    const int lt = lane & 3;

    float acc[4][4][4];
#pragma unroll
    for (int mi = 0; mi < 4; mi++)
#pragma unroll
        for (int ni = 0; ni < 4; ni++)
#pragma unroll
            for (int r = 0; r < 4; r++) acc[mi][ni][r] = 0.0f;

    float4 ar[4], br0[2], br1[2];
    auto ldg_chunk = [&](int it) {
#pragma unroll
        for (int i = 0; i < 4; i++) {
            int s = tid + i * 256;
            int row = s >> 3, c4 = (s & 7) * 4;
            ar[i] = *(const float4*)&A[(size_t)(bm + row) * EE + it * 32 + c4];
        }
#pragma unroll
        for (int i = 0; i < 2; i++) {
            int s = tid + i * 256;
            int kp = s >> 5, c4 = (s & 31) * 4;
            br0[i] = *(const float4*)&W[(size_t)(it * 32 + 2 * kp) * EE + bn + c4];
            br1[i] = *(const float4*)&W[(size_t)(it * 32 + 2 * kp + 1) * EE + bn + c4];
        }
    };
    ldg_chunk(0);

    for (int it = 0; it < 32; it++) {
        __syncthreads();
#pragma unroll
        for (int i = 0; i < 4; i++) {
            int s = tid + i * 256;
            int row = s >> 3, c4 = (s & 7) * 4;
            uint32_t h0, l0, h1, l1;
            bf_split2(ar[i].x, ar[i].y, h0, l0);
            bf_split2(ar[i].z, ar[i].w, h1, l1);
            *(uint4*)&Ah[row * GA_STR + c4 / 2] = make_uint4(h0, l0, h1, l1);
        }
#pragma unroll
        for (int i = 0; i < 2; i++) {
            int s = tid + i * 256;
            int kp = s >> 5, c4 = (s & 31) * 4;
            uint32_t h, l;
            uint4 w0, w1;
            bf_split2(br0[i].x, br1[i].x, h, l); w0.x = h; w0.y = l;
            bf_split2(br0[i].y, br1[i].y, h, l); w0.z = h; w0.w = l;
            bf_split2(br0[i].z, br1[i].z, h, l); w1.x = h; w1.y = l;
            bf_split2(br0[i].w, br1[i].w, h, l); w1.z = h; w1.w = l;
            *(uint4*)&Bh[kp * GB_STR + c4] = w0;
            *(uint4*)&Bh[kp * GB_STR + c4 + 2] = w1;
        }
        __syncthreads();
        if (it + 1 < 32) ldg_chunk(it + 1);

#pragma unroll
        for (int ks = 0; ks < 2; ks++) {
            uint32_t ah[4][4], al[4][4];
#pragma unroll
            for (int mi = 0; mi < 4; mi++) {
                int r = warpM * 64 + mi * 16 + lg;
                uint2 a0 = Ah[r * GA_STR + ks * 8 + lt];
                uint2 a1 = Ah[(r + 8) * GA_STR + ks * 8 + lt];
                uint2 a2 = Ah[r * GA_STR + ks * 8 + lt + 4];
                uint2 a3 = Ah[(r + 8) * GA_STR + ks * 8 + lt + 4];
                ah[mi][0] = a0.x; ah[mi][1] = a1.x; ah[mi][2] = a2.x; ah[mi][3] = a3.x;
                al[mi][0] = a0.y; al[mi][1] = a1.y; al[mi][2] = a2.y; al[mi][3] = a3.y;
            }
            uint32_t bh[4][2], bl[4][2];
#pragma unroll
            for (int ni = 0; ni < 4; ni++) {
                int col = warpN * 32 + ni * 8 + lg;
                uint2 b0 = Bh[(ks * 8 + lt) * GB_STR + col];
                uint2 b1 = Bh[(ks * 8 + lt + 4) * GB_STR + col];
                bh[ni][0] = b0.x; bh[ni][1] = b1.x;
                bl[ni][0] = b0.y; bl[ni][1] = b1.y;
            }
#pragma unroll
            for (int mi = 0; mi < 4; mi++)
#pragma unroll
                for (int ni = 0; ni < 4; ni++) {
                    mma_bf16(acc[mi][ni], ah[mi], bh[ni]);
                    mma_bf16(acc[mi][ni], al[mi], bh[ni]);
                    mma_bf16(acc[mi][ni], ah[mi], bl[ni]);
                }
        }
    }

#pragma unroll
    for (int mi = 0; mi < 4; mi++) {
        const int row0 = bm + warpM * 64 + mi * 16 + lg;
#pragma unroll
        for (int ni = 0; ni < 4; ni++) {
            const int col = bn + warpN * 32 + ni * 8 + lt * 2;
            const float b0 = bias[col], b1 = bias[col + 1];
            float2 v0 = make_float2(acc[mi][ni][0] + b0, acc[mi][ni][1] + b1);
            float2 v1 = make_float2(acc[mi][ni][2] + b0, acc[mi][ni][3] + b1);
            *(float2*)&C[(size_t)row0 * EE + col] = v0;
            *(float2*)&C[(size_t)(row0 + 8) * EE + col] = v1;
        }
    }
}

__global__ __launch_bounds__(256, 1)
void gemm_qkv(const float* __restrict__ q, const float* __restrict__ k,
              const float* __restrict__ v,
              const float* __restrict__ Wq, const float* __restrict__ Wk,
              const float* __restrict__ Wv,
              const float* __restrict__ bq, const float* __restrict__ bk,
              const float* __restrict__ bv,
              float* __restrict__ qp, float* __restrict__ kp,
              float* __restrict__ vp)
{
    const int z = blockIdx.z;
    const float* A = (z == 0) ? q : (z == 1) ? k : v;
    const float* W = (z == 0) ? Wq : (z == 1) ? Wk : Wv;
    const float* bias = (z == 0) ? bq : (z == 1) ? bk : bv;
    float* C = (z == 0) ? qp : (z == 1) ? kp : vp;
    gemm_body(A, W, bias, C);
}

__global__ __launch_bounds__(256, 1)
void gemm_one(const float* __restrict__ A, const float* __restrict__ W,
              const float* __restrict__ bias, float* __restrict__ C)
{
    gemm_body(A, W, bias, C);
}

// ================= Flash attention (causal), bf16 3-term split ==============
#define PK_STR 36
#define FV_STR 68
#define P_U2 (128 * PK_STR)
#define OFF_K_U2 P_U2
#define OFF_V_U2 (OFF_K_U2 + 64 * PK_STR)
#define FLASH5_U2 (OFF_V_U2 + 32 * FV_STR)
#define FLASH5_B (FLASH5_U2 * 8)   // 72704 bytes
#define QR_STR 68

__global__ __launch_bounds__(256, 1)
void flash_mma_kernel(const float* __restrict__ Qp,
                      const float* __restrict__ Kp,
                      const float* __restrict__ Vp,
                      float* __restrict__ Out)
{
    extern __shared__ uint2 su[];
    float* Qr = (float*)su;
    uint2* Ph = su;
    uint2* Kh = su + OFF_K_U2;
    uint2* Vh = su + OFF_V_U2;

    const int tid = threadIdx.x;
    const int lane = tid & 31;
    const int w = tid >> 5;
    const int lg = lane >> 2;
    const int lt = lane & 3;
    const int qt = (gridDim.x - 1) - blockIdx.x;
    const int h = blockIdx.y;
    const int b = blockIdx.z;
    const int qbase = qt * 128;
    const size_t head = (size_t)h * DD;

    const float QSCALE = 0.18033688011112042591f;   // 0.125 * log2(e)
    for (int i = tid; i < 128 * 16; i += 256) {
        int row = i >> 4, c4 = (i & 15) * 4;
        float4 q4 = *(const float4*)&Qp[((size_t)(b * SS + qbase + row)) * EE + head + c4];
        q4.x *= QSCALE; q4.y *= QSCALE; q4.z *= QSCALE; q4.w *= QSCALE;
        *(float4*)&Qr[row * QR_STR + c4] = q4;
    }
    __syncthreads();

    const int r0 = w * 16 + lg;
    uint32_t qh[4][4], ql[4][4];
#pragma unroll
    for (int ks = 0; ks < 4; ks++) {
        float2 x0 = *(float2*)&Qr[r0 * QR_STR + 2 * (ks * 8 + lt)];
        float2 x1 = *(float2*)&Qr[(r0 + 8) * QR_STR + 2 * (ks * 8 + lt)];
        float2 x2 = *(float2*)&Qr[r0 * QR_STR + 2 * (ks * 8 + lt + 4)];
        float2 x3 = *(float2*)&Qr[(r0 + 8) * QR_STR + 2 * (ks * 8 + lt + 4)];
        bf_split2(x0.x, x0.y, qh[ks][0], ql[ks][0]);
        bf_split2(x1.x, x1.y, qh[ks][1], ql[ks][1]);
        bf_split2(x2.x, x2.y, qh[ks][2], ql[ks][2]);
        bf_split2(x3.x, x3.y, qh[ks][3], ql[ks][3]);
    }

    float oacc[8][4];
#pragma unroll
    for (int ni = 0; ni < 8; ni++)
#pragma unroll
        for (int r = 0; r < 4; r++) oacc[ni][r] = 0.0f;
    float m0 = -1e30f, m1 = -1e30f, l0 = 0.0f, l1 = 0.0f;

    const int nkt = (qbase + 128) / 64;

    for (int kt = 0; kt < nkt; kt++) {
        const int kbase = kt * 64;
        __syncthreads();
#pragma unroll
        for (int i = 0; i < 4; i++) {
            int s = tid + i * 256;
            int row = s >> 4, c4 = (s & 15) * 4;
            float4 k4 = *(const float4*)&Kp[((size_t)(b * SS + kbase + row)) * EE + head + c4];
            uint32_t h0, lo0, h1, lo1;
            bf_split2(k4.x, k4.y, h0, lo0);
            bf_split2(k4.z, k4.w, h1, lo1);
            *(uint4*)&Kh[row * PK_STR + c4 / 2] = make_uint4(h0, lo0, h1, lo1);
        }
#pragma unroll
        for (int i = 0; i < 2; i++) {
            int s = tid + i * 256;
            int kp = s >> 4, c4 = (s & 15) * 4;
            const size_t g0 = ((size_t)(b * SS + kbase + 2 * kp)) * EE + head + c4;
            float4 va = *(const float4*)&Vp[g0];
            float4 vb = *(const float4*)&Vp[g0 + EE];
            uint32_t hh, ll;
            uint4 w0, w1;
            bf_split2(va.x, vb.x, hh, ll); w0.x = hh; w0.y = ll;
            bf_split2(va.y, vb.y, hh, ll); w0.z = hh; w0.w = ll;
            bf_split2(va.z, vb.z, hh, ll); w1.x = hh; w1.y = ll;
            bf_split2(va.w, vb.w, hh, ll); w1.z = hh; w1.w = ll;
            *(uint4*)&Vh[kp * FV_STR + c4] = w0;
            *(uint4*)&Vh[kp * FV_STR + c4 + 2] = w1;
        }
        __syncthreads();

        float sacc[8][4];
#pragma unroll
        for (int ni = 0; ni < 8; ni++)
#pragma unroll
            for (int r = 0; r < 4; r++) sacc[ni][r] = 0.0f;

#pragma unroll
        for (int ks = 0; ks < 4; ks++) {
#pragma unroll
            for (int ni = 0; ni < 8; ni++) {
                const int krow = ni * 8 + lg;
                uint2 k0 = Kh[krow * PK_STR + ks * 8 + lt];
                uint2 k1 = Kh[krow * PK_STR + ks * 8 + lt + 4];
                uint32_t bh[2] = {k0.x, k1.x};
                uint32_t bl[2] = {k0.y, k1.y};
                mma_bf16(sacc[ni], qh[ks], bh);
                mma_bf16(sacc[ni], ql[ks], bh);
                mma_bf16(sacc[ni], qh[ks], bl);
            }
        }

        if (kt >= 2 * qt) {
            const int grow0 = qbase + r0;
#pragma unroll
            for (int ni = 0; ni < 8; ni++) {
                const int c0 = kbase + ni * 8 + lt * 2;
                if (c0 > grow0)         sacc[ni][0] = -1e30f;
                if (c0 + 1 > grow0)     sacc[ni][1] = -1e30f;
                if (c0 > grow0 + 8)     sacc[ni][2] = -1e30f;
                if (c0 + 1 > grow0 + 8) sacc[ni][3] = -1e30f;
            }
        }

        float rmax0 = -1e30f, rmax1 = -1e30f;
#pragma unroll
        for (int ni = 0; ni < 8; ni++) {
            rmax0 = fmaxf(rmax0, fmaxf(sacc[ni][0], sacc[ni][1]));
            rmax1 = fmaxf(rmax1, fmaxf(sacc[ni][2], sacc[ni][3]));
        }
        rmax0 = fmaxf(rmax0, __shfl_xor_sync(0xffffffffu, rmax0, 1));
        rmax0 = fmaxf(rmax0, __shfl_xor_sync(0xffffffffu, rmax0, 2));
        rmax1 = fmaxf(rmax1, __shfl_xor_sync(0xffffffffu, rmax1, 1));
        rmax1 = fmaxf(rmax1, __shfl_xor_sync(0xffffffffu, rmax1, 2));

        const float newm0 = fmaxf(m0, rmax0);
        const float newm1 = fmaxf(m1, rmax1);
        const float alpha0 = ex2(m0 - newm0);
        const float alpha1 = ex2(m1 - newm1);
        m0 = newm0; m1 = newm1;

        float rsum0 = 0.0f, rsum1 = 0.0f;
#pragma unroll
        for (int ni = 0; ni < 8; ni++) {
            sacc[ni][0] = ex2(sacc[ni][0] - m0);
            sacc[ni][1] = ex2(sacc[ni][1] - m0);
            sacc[ni][2] = ex2(sacc[ni][2] - m1);
            sacc[ni][3] = ex2(sacc[ni][3] - m1);
            rsum0 += sacc[ni][0] + sacc[ni][1];
            rsum1 += sacc[ni][2] + sacc[ni][3];
        }
        rsum0 += __shfl_xor_sync(0xffffffffu, rsum0, 1);
        rsum0 += __shfl_xor_sync(0xffffffffu, rsum0, 2);
        rsum1 += __shfl_xor_sync(0xffffffffu, rsum1, 1);
        rsum1 += __shfl_xor_sync(0xffffffffu, rsum1, 2);
        l0 = l0 * alpha0 + rsum0;
        l1 = l1 * alpha1 + rsum1;

#pragma unroll
        for (int ni = 0; ni < 8; ni++) {
            oacc[ni][0] *= alpha0;
            oacc[ni][1] *= alpha0;
            oacc[ni][2] *= alpha1;
            oacc[ni][3] *= alpha1;
            uint32_t hh, ll;
            bf_split2(sacc[ni][0], sacc[ni][1], hh, ll);
            Ph[r0 * PK_STR + ni * 4 + lt] = make_uint2(hh, ll);
            bf_split2(sacc[ni][2], sacc[ni][3], hh, ll);
            Ph[(r0 + 8) * PK_STR + ni * 4 + lt] = make_uint2(hh, ll);
        }
        __syncwarp();

#pragma unroll
        for (int ks = 0; ks < 4; ks++) {
            uint2 p0 = Ph[r0 * PK_STR + ks * 8 + lt];
            uint2 p1 = Ph[(r0 + 8) * PK_STR + ks * 8 + lt];
            uint2 p2 = Ph[r0 * PK_STR + ks * 8 + lt + 4];
            uint2 p3 = Ph[(r0 + 8) * PK_STR + ks * 8 + lt + 4];
            uint32_t ph[4] = {p0.x, p1.x, p2.x, p3.x};
            uint32_t pl[4] = {p0.y, p1.y, p2.y, p3.y};
#pragma unroll
            for (int ni = 0; ni < 8; ni++) {
                const int col = ni * 8 + lg;
                uint2 v0 = Vh[(ks * 8 + lt) * FV_STR + col];
                uint2 v1 = Vh[(ks * 8 + lt + 4) * FV_STR + col];
                uint32_t bh[2] = {v0.x, v1.x};
                uint32_t bl[2] = {v0.y, v1.y};
                mma_bf16(oacc[ni], ph, bh);
                mma_bf16(oacc[ni], pl, bh);
                mma_bf16(oacc[ni], ph, bl);
            }
        }
    }

    const float inv0 = 1.0f / l0;
    const float inv1 = 1.0f / l1;
    const int grow = qbase + r0;
#pragma unroll
    for (int ni = 0; ni < 8; ni++) {
        const size_t col = head + ni * 8 + lt * 2;
        *(float2*)&Out[((size_t)(b * SS + grow)) * EE + col] =
            make_float2(oacc[ni][0] * inv0, oacc[ni][1] * inv0);
        *(float2*)&Out[((size_t)(b * SS + grow + 8)) * EE + col] =
            make_float2(oacc[ni][2] * inv1, oacc[ni][3] * inv1);
    }
}

// ---------------- launch ----------------------------------------------------
extern "C" void kernel_launch(void* const* d_in, const int* in_sizes, int n_in,
                              void* d_out, int out_size)
{
    const float* q  = (const float*)d_in[0];
    const float* k  = (const float*)d_in[1];
    const float* v  = (const float*)d_in[2];
    const float* Wq = (const float*)d_in[3];
    const float* bq = (const float*)d_in[4];
    const float* Wk = (const float*)d_in[5];
    const float* bk = (const float*)d_in[6];
    const float* Wv = (const float*)d_in[7];
    const float* bv = (const float*)d_in[8];
    const float* Wo = (const float*)d_in[9];
    const float* bo = (const float*)d_in[10];
    float* out = (float*)d_out;

    float* qp; cudaGetSymbolAddress((void**)&qp, g_qp);
    float* kp; cudaGetSymbolAddress((void**)&kp, g_kp);
    float* vp; cudaGetSymbolAddress((void**)&vp, g_vp);
    float* at; cudaGetSymbolAddress((void**)&at, g_at);

    cudaFuncSetAttribute(gemm_qkv,
                         cudaFuncAttributeMaxDynamicSharedMemorySize, GEMM3_B);
    cudaFuncSetAttribute(gemm_one,
                         cudaFuncAttributeMaxDynamicSharedMemorySize, GEMM3_B);
    cudaFuncSetAttribute(flash_mma_kernel,
                         cudaFuncAttributeMaxDynamicSharedMemorySize, FLASH5_B);

    dim3 qkv_grid(EE / 128, MM / 128, 3);
    gemm_qkv<<<qkv_grid, 256, GEMM3_B>>>(q, k, v, Wq, Wk, Wv, bq, bk, bv,
                                         qp, kp, vp);

    dim3 fa_grid(SS / 128, HH, BB);
    flash_mma_kernel<<<fa_grid, 256, FLASH5_B>>>(qp, kp, vp, at);

    dim3 ggrid(EE / 128, MM / 128);
    gemm_one<<<ggrid, 256, GEMM3_B>>>(at, Wo, bo, out);
}

// round 12
// speedup vs baseline: 3.3039x; 1.1142x over previous
#include <cuda_runtime.h>
#include <cuda_bf16.h>
#include <math.h>
#include <stdint.h>

#define BB 2
#define SS 2048
#define EE 1024
#define HH 16
#define DD 64
#define MM (BB * SS)
#define KP 512          // k-pairs per row (EE/2)

// ---------------- scratch (device globals; no allocations allowed) ----------
__device__ uint2 g_wsp[4][KP * EE];     // weights split: [kpair][n] {hi2,lo2}
__device__ uint2 g_asp[3][MM * KP];     // input activations split: [row][kpair]
__device__ uint2 g_qsp[MM * KP];        // projected Q, scaled+split
__device__ uint2 g_ksp[MM * KP];        // projected K, split
__device__ float g_vp [MM * EE];        // projected V, fp32
__device__ uint2 g_atsp[MM * KP];       // attention output, split

// ======================= helpers ============================================
__device__ __forceinline__ uint32_t smem_u32(const void* p) {
    uint32_t a;
    asm("{ .reg .u64 t; cvta.to.shared.u64 t, %1; cvt.u32.u64 %0, t; }"
        : "=r"(a) : "l"(p));
    return a;
}
__device__ __forceinline__ void cp16(uint32_t dst, const void* src) {
    asm volatile("cp.async.cg.shared.global [%0], [%1], 16;" :: "r"(dst), "l"(src));
}
#define CP_COMMIT() asm volatile("cp.async.commit_group;" ::: "memory")
#define CP_WAIT0()  asm volatile("cp.async.wait_group 0;" ::: "memory")
#define CP_WAIT1()  asm volatile("cp.async.wait_group 1;" ::: "memory")
#define CP_WAIT2()  asm volatile("cp.async.wait_group 2;" ::: "memory")

__device__ __forceinline__ uint32_t packbf(float x0, float x1) {
    uint32_t r;
    asm("cvt.rn.bf16x2.f32 %0, %1, %2;" : "=r"(r) : "f"(x1), "f"(x0));
    return r;
}
__device__ __forceinline__ void bf_split2(float x0, float x1,
                                          uint32_t& h2, uint32_t& l2) {
    h2 = packbf(x0, x1);
    float h0 = __uint_as_float(h2 << 16);
    float h1 = __uint_as_float(h2 & 0xffff0000u);
    l2 = packbf(x0 - h0, x1 - h1);
}
__device__ __forceinline__ float ex2(float x) {
    float r;
    asm("ex2.approx.f32 %0, %1;" : "=f"(r) : "f"(x));
    return r;
}
__device__ __forceinline__ void mma_bf16(float* d, const uint32_t* a, const uint32_t* b) {
    asm volatile(
        "mma.sync.aligned.m16n8k16.row.col.f32.bf16.bf16.f32 "
        "{%0,%1,%2,%3}, {%4,%5,%6,%7}, {%8,%9}, {%0,%1,%2,%3};"
        : "+f"(d[0]), "+f"(d[1]), "+f"(d[2]), "+f"(d[3])
        : "r"(a[0]), "r"(a[1]), "r"(a[2]), "r"(a[3]), "r"(b[0]), "r"(b[1]));
}

// ======================= pre-split kernels ==================================
// Weights: pair = two adjacent k rows, per column n.
__global__ __launch_bounds__(256)
void split_w(const float* __restrict__ W0, const float* __restrict__ W1,
             const float* __restrict__ W2, const float* __restrict__ W3)
{
    const int z = blockIdx.z;
    const float* W = (z == 0) ? W0 : (z == 1) ? W1 : (z == 2) ? W2 : W3;
    uint2* out = g_wsp[z];
    const int idx = blockIdx.x * 256 + threadIdx.x;   // 512*256 = 131072
    const int kp = idx >> 8;
    const int n = (idx & 255) * 4;
    float4 r0 = *(const float4*)&W[(size_t)(2 * kp) * EE + n];
    float4 r1 = *(const float4*)&W[(size_t)(2 * kp + 1) * EE + n];
    uint32_t hh, ll;
    bf_split2(r0.x, r1.x, hh, ll); out[(size_t)kp * EE + n + 0] = make_uint2(hh, ll);
    bf_split2(r0.y, r1.y, hh, ll); out[(size_t)kp * EE + n + 1] = make_uint2(hh, ll);
    bf_split2(r0.z, r1.z, hh, ll); out[(size_t)kp * EE + n + 2] = make_uint2(hh, ll);
    bf_split2(r0.w, r1.w, hh, ll); out[(size_t)kp * EE + n + 3] = make_uint2(hh, ll);
}

// Activations: pair = two adjacent k within a row.
__global__ __launch_bounds__(256)
void split_act(const float* __restrict__ q, const float* __restrict__ k,
               const float* __restrict__ v)
{
    const int z = blockIdx.z;
    const float* src = (z == 0) ? q : (z == 1) ? k : v;
    uint2* out = g_asp[z];
    const int idx = blockIdx.x * 256 + threadIdx.x;   // 4096*256
    const int row = idx >> 8;
    const int c = (idx & 255) * 4;
    float4 x = *(const float4*)&src[(size_t)row * EE + c];
    uint32_t hh, ll;
    bf_split2(x.x, x.y, hh, ll); out[(size_t)row * KP + c / 2]     = make_uint2(hh, ll);
    bf_split2(x.z, x.w, hh, ll); out[(size_t)row * KP + c / 2 + 1] = make_uint2(hh, ll);
}

// ======================= GEMM: pre-split operands, zero CVT =================
// C = A @ W + bias, 128x128 tile, K-chunk 32, 8 warps, m16n8k16 3-term split.
// 4-stage cp.async pipeline, ONE sync per iteration.
#define GA_STR 20            // A smem stride (uint2)
#define GB_STR 132           // B smem stride (uint2)
#define ST_A_U2 (128 * GA_STR)          // 2560
#define ST_B_U2 (16 * GB_STR)           // 2112
#define ST_U2 (ST_A_U2 + ST_B_U2)       // 4672
#define GEMM4_B (4 * ST_U2 * 8)         // 149504 bytes

#define QSCALE 0.18033688011112042591f  // 0.125 * log2(e)

__device__ __forceinline__ void gemm_body(const uint2* __restrict__ Asp,
                                          const uint2* __restrict__ Wsp,
                                          const float* __restrict__ bias,
                                          float* __restrict__ Cf,
                                          uint2* __restrict__ Cp,
                                          int mode)   // 0:Q split+scale 1:K split 2/3: fp32
{
    extern __shared__ uint2 su[];
    const uint32_t sb0 = smem_u32(su);

    const int tid = threadIdx.x;
    const int lane = tid & 31;
    const int wid = tid >> 5;
    const int warpM = wid >> 2;
    const int warpN = wid & 3;
    const int bm = blockIdx.y * 128;
    const int bn = blockIdx.x * 128;
    const int lg = lane >> 2;
    const int lt = lane & 3;

    float acc[4][4][4];
#pragma unroll
    for (int mi = 0; mi < 4; mi++)
#pragma unroll
        for (int ni = 0; ni < 4; ni++)
#pragma unroll
            for (int r = 0; r < 4; r++) acc[mi][ni][r] = 0.0f;

    auto load = [&](int it) {
        const int st = it & 3;
        const uint32_t sa = sb0 + (uint32_t)(st * ST_U2) * 8;
        const uint32_t sbp = sa + ST_A_U2 * 8;
#pragma unroll
        for (int i = 0; i < 4; i++) {
            int cid = tid + i * 256;
            int row = cid >> 3, c2 = (cid & 7) * 2;
            cp16(sa + (uint32_t)(row * GA_STR + c2) * 8,
                 Asp + (size_t)(bm + row) * KP + it * 16 + c2);
        }
#pragma unroll
        for (int i = 0; i < 4; i++) {
            int cid = tid + i * 256;
            int kp = cid >> 6, c = (cid & 63) * 2;
            cp16(sbp + (uint32_t)(kp * GB_STR + c) * 8,
                 Wsp + (size_t)(it * 16 + kp) * EE + bn + c);
        }
    };

    load(0); CP_COMMIT();
    load(1); CP_COMMIT();
    load(2); CP_COMMIT();

    for (int it = 0; it < 32; it++) {
        if (it < 30) { CP_WAIT2(); } else if (it == 30) { CP_WAIT1(); } else { CP_WAIT0(); }
        __syncthreads();
        if (it + 3 < 32) { load(it + 3); CP_COMMIT(); }

        const uint2* Ah = su + (it & 3) * ST_U2;
        const uint2* Bh = Ah + ST_A_U2;

#pragma unroll
        for (int ks = 0; ks < 2; ks++) {
            uint32_t ah[4][4], al[4][4];
#pragma unroll
            for (int mi = 0; mi < 4; mi++) {
                int r = warpM * 64 + mi * 16 + lg;
                uint2 a0 = Ah[r * GA_STR + ks * 8 + lt];
                uint2 a1 = Ah[(r + 8) * GA_STR + ks * 8 + lt];
                uint2 a2 = Ah[r * GA_STR + ks * 8 + lt + 4];
                uint2 a3 = Ah[(r + 8) * GA_STR + ks * 8 + lt + 4];
                ah[mi][0] = a0.x; ah[mi][1] = a1.x; ah[mi][2] = a2.x; ah[mi][3] = a3.x;
                al[mi][0] = a0.y; al[mi][1] = a1.y; al[mi][2] = a2.y; al[mi][3] = a3.y;
            }
            uint32_t bh[4][2], bl[4][2];
#pragma unroll
            for (int ni = 0; ni < 4; ni++) {
                int col = warpN * 32 + ni * 8 + lg;
                uint2 b0 = Bh[(ks * 8 + lt) * GB_STR + col];
                uint2 b1 = Bh[(ks * 8 + lt + 4) * GB_STR + col];
                bh[ni][0] = b0.x; bh[ni][1] = b1.x;
                bl[ni][0] = b0.y; bl[ni][1] = b1.y;
            }
#pragma unroll
            for (int mi = 0; mi < 4; mi++)
#pragma unroll
                for (int ni = 0; ni < 4; ni++) {
                    mma_bf16(acc[mi][ni], ah[mi], bh[ni]);
                    mma_bf16(acc[mi][ni], al[mi], bh[ni]);
                    mma_bf16(acc[mi][ni], ah[mi], bl[ni]);
                }
        }
    }

    // ---- epilogue
    if (mode <= 1) {
        const float s = (mode == 0) ? QSCALE : 1.0f;
#pragma unroll
        for (int mi = 0; mi < 4; mi++) {
            const int row0 = bm + warpM * 64 + mi * 16 + lg;
#pragma unroll
            for (int ni = 0; ni < 4; ni++) {
                const int col = bn + warpN * 32 + ni * 8 + lt * 2;
                const float b0 = bias[col], b1 = bias[col + 1];
                uint32_t hh, ll;
                bf_split2((acc[mi][ni][0] + b0) * s, (acc[mi][ni][1] + b1) * s, hh, ll);
                Cp[(size_t)row0 * KP + col / 2] = make_uint2(hh, ll);
                bf_split2((acc[mi][ni][2] + b0) * s, (acc[mi][ni][3] + b1) * s, hh, ll);
                Cp[(size_t)(row0 + 8) * KP + col / 2] = make_uint2(hh, ll);
            }
        }
    } else {
#pragma unroll
        for (int mi = 0; mi < 4; mi++) {
            const int row0 = bm + warpM * 64 + mi * 16 + lg;
#pragma unroll
            for (int ni = 0; ni < 4; ni++) {
                const int col = bn + warpN * 32 + ni * 8 + lt * 2;
                const float b0 = bias[col], b1 = bias[col + 1];
                float2 v0 = make_float2(acc[mi][ni][0] + b0, acc[mi][ni][1] + b1);
                float2 v1 = make_float2(acc[mi][ni][2] + b0, acc[mi][ni][3] + b1);
                *(float2*)&Cf[(size_t)row0 * EE + col] = v0;
                *(float2*)&Cf[(size_t)(row0 + 8) * EE + col] = v1;
            }
        }
    }
}

__global__ __launch_bounds__(256, 1)
void gemm_qkv(const float* __restrict__ bq, const float* __restrict__ bk,
              const float* __restrict__ bv)
{
    const int z = blockIdx.z;
    const float* bias = (z == 0) ? bq : (z == 1) ? bk : bv;
    if (z == 0)      gemm_body(g_asp[0], g_wsp[0], bias, nullptr, g_qsp, 0);
    else if (z == 1) gemm_body(g_asp[1], g_wsp[1], bias, nullptr, g_ksp, 1);
    else             gemm_body(g_asp[2], g_wsp[2], bias, g_vp, nullptr, 2);
}

__global__ __launch_bounds__(256, 1)
void gemm_out(const float* __restrict__ bo, float* __restrict__ out)
{
    gemm_body(g_atsp, g_wsp[3], bo, out, nullptr, 3);
}

// ================= Flash attention: pre-split Q/K, zero-CVT K path ==========
#define PK_STR 36
#define FV_STR 68
#define OFF_K_U2 (128 * PK_STR)             // 4608 (after Ph)
#define OFF_V_U2 (OFF_K_U2 + 64 * PK_STR)   // 6912
#define FLASH6_U2 (OFF_V_U2 + 32 * FV_STR)  // 9088
#define FLASH6_B (FLASH6_U2 * 8)            // 72704 bytes

__global__ __launch_bounds__(256, 1)
void flash_mma_kernel()
{
    extern __shared__ uint2 su[];
    uint2* Ph = su;
    uint2* Kh = su + OFF_K_U2;
    uint2* Vh = su + OFF_V_U2;

    const int tid = threadIdx.x;
    const int lane = tid & 31;
    const int w = tid >> 5;
    const int lg = lane >> 2;
    const int lt = lane & 3;
    const int qt = (gridDim.x - 1) - blockIdx.x;
    const int hd = blockIdx.y;
    const int b = blockIdx.z;
    const int qbase = qt * 128;
    const int hp = hd * 32;                  // head offset in pairs

    // Q fragments: direct LDG of pre-split, pre-scaled pairs
    const int r0 = w * 16 + lg;
    uint32_t qh[4][4], ql[4][4];
    {
        const size_t base0 = (size_t)(b * SS + qbase + r0) * KP + hp;
        const size_t base1 = base0 + 8 * KP;
#pragma unroll
        for (int ks = 0; ks < 4; ks++) {
            uint2 a0 = g_qsp[base0 + ks * 8 + lt];
            uint2 a1 = g_qsp[base1 + ks * 8 + lt];
            uint2 a2 = g_qsp[base0 + ks * 8 + lt + 4];
            uint2 a3 = g_qsp[base1 + ks * 8 + lt + 4];
            qh[ks][0] = a0.x; qh[ks][1] = a1.x; qh[ks][2] = a2.x; qh[ks][3] = a3.x;
            ql[ks][0] = a0.y; ql[ks][1] = a1.y; ql[ks][2] = a2.y; ql[ks][3] = a3.y;
        }
    }

    float oacc[8][4];
#pragma unroll
    for (int ni = 0; ni < 8; ni++)
#pragma unroll
        for (int r = 0; r < 4; r++) oacc[ni][r] = 0.0f;
    float m0 = -1e30f, m1 = -1e30f, l0 = 0.0f, l1 = 0.0f;

    const int nkt = (qbase + 128) / 64;

    for (int kt = 0; kt < nkt; kt++) {
        const int kbase = kt * 64;
        __syncthreads();
        // K tile: cp.async of pre-split pairs (zero CVT)
#pragma unroll
        for (int i = 0; i < 4; i++) {
            int cid = tid + i * 256;
            int row = cid >> 4, c2 = (cid & 15) * 2;
            cp16(smem_u32(Kh + row * PK_STR + c2),
                 g_ksp + (size_t)(b * SS + kbase + row) * KP + hp + c2);
        }
        CP_COMMIT();
        // V tile: fp32 -> split (pairs along key)
#pragma unroll
        for (int i = 0; i < 2; i++) {
            int s = tid + i * 256;
            int kp = s >> 4, c4 = (s & 15) * 4;
            const size_t g0 = ((size_t)(b * SS + kbase + 2 * kp)) * EE + hd * DD + c4;
            float4 va = *(const float4*)&g_vp[g0];
            float4 vb = *(const float4*)&g_vp[g0 + EE];
            uint32_t hh, ll;
            uint4 w0, w1;
            bf_split2(va.x, vb.x, hh, ll); w0.x = hh; w0.y = ll;
            bf_split2(va.y, vb.y, hh, ll); w0.z = hh; w0.w = ll;
            bf_split2(va.z, vb.z, hh, ll); w1.x = hh; w1.y = ll;
            bf_split2(va.w, vb.w, hh, ll); w1.z = hh; w1.w = ll;
            *(uint4*)&Vh[kp * FV_STR + c4] = w0;
            *(uint4*)&Vh[kp * FV_STR + c4 + 2] = w1;
        }
        CP_WAIT0();
        __syncthreads();

        // ---- S = Q @ K^T
        float sacc[8][4];
#pragma unroll
        for (int ni = 0; ni < 8; ni++)
#pragma unroll
            for (int r = 0; r < 4; r++) sacc[ni][r] = 0.0f;

#pragma unroll
        for (int ks = 0; ks < 4; ks++) {
#pragma unroll
            for (int ni = 0; ni < 8; ni++) {
                const int krow = ni * 8 + lg;
                uint2 k0 = Kh[krow * PK_STR + ks * 8 + lt];
                uint2 k1 = Kh[krow * PK_STR + ks * 8 + lt + 4];
                uint32_t bh[2] = {k0.x, k1.x};
                uint32_t bl[2] = {k0.y, k1.y};
                mma_bf16(sacc[ni], qh[ks], bh);
                mma_bf16(sacc[ni], ql[ks], bh);
                mma_bf16(sacc[ni], qh[ks], bl);
            }
        }

        if (kt >= 2 * qt) {
            const int grow0 = qbase + r0;
#pragma unroll
            for (int ni = 0; ni < 8; ni++) {
                const int c0 = kbase + ni * 8 + lt * 2;
                if (c0 > grow0)         sacc[ni][0] = -1e30f;
                if (c0 + 1 > grow0)     sacc[ni][1] = -1e30f;
                if (c0 > grow0 + 8)     sacc[ni][2] = -1e30f;
                if (c0 + 1 > grow0 + 8) sacc[ni][3] = -1e30f;
            }
        }

        float rmax0 = -1e30f, rmax1 = -1e30f;
#pragma unroll
        for (int ni = 0; ni < 8; ni++) {
            rmax0 = fmaxf(rmax0, fmaxf(sacc[ni][0], sacc[ni][1]));
            rmax1 = fmaxf(rmax1, fmaxf(sacc[ni][2], sacc[ni][3]));
        }
        rmax0 = fmaxf(rmax0, __shfl_xor_sync(0xffffffffu, rmax0, 1));
        rmax0 = fmaxf(rmax0, __shfl_xor_sync(0xffffffffu, rmax0, 2));
        rmax1 = fmaxf(rmax1, __shfl_xor_sync(0xffffffffu, rmax1, 1));
        rmax1 = fmaxf(rmax1, __shfl_xor_sync(0xffffffffu, rmax1, 2));

        const float newm0 = fmaxf(m0, rmax0);
        const float newm1 = fmaxf(m1, rmax1);
        const float alpha0 = ex2(m0 - newm0);
        const float alpha1 = ex2(m1 - newm1);
        m0 = newm0; m1 = newm1;

        float rsum0 = 0.0f, rsum1 = 0.0f;
#pragma unroll
        for (int ni = 0; ni < 8; ni++) {
            sacc[ni][0] = ex2(sacc[ni][0] - m0);
            sacc[ni][1] = ex2(sacc[ni][1] - m0);
            sacc[ni][2] = ex2(sacc[ni][2] - m1);
            sacc[ni][3] = ex2(sacc[ni][3] - m1);
            rsum0 += sacc[ni][0] + sacc[ni][1];
            rsum1 += sacc[ni][2] + sacc[ni][3];
        }
        rsum0 += __shfl_xor_sync(0xffffffffu, rsum0, 1);
        rsum0 += __shfl_xor_sync(0xffffffffu, rsum0, 2);
        rsum1 += __shfl_xor_sync(0xffffffffu, rsum1, 1);
        rsum1 += __shfl_xor_sync(0xffffffffu, rsum1, 2);
        l0 = l0 * alpha0 + rsum0;
        l1 = l1 * alpha1 + rsum1;

#pragma unroll
        for (int ni = 0; ni < 8; ni++) {
            oacc[ni][0] *= alpha0;
            oacc[ni][1] *= alpha0;
            oacc[ni][2] *= alpha1;
            oacc[ni][3] *= alpha1;
            uint32_t hh, ll;
            bf_split2(sacc[ni][0], sacc[ni][1], hh, ll);
            Ph[r0 * PK_STR + ni * 4 + lt] = make_uint2(hh, ll);
            bf_split2(sacc[ni][2], sacc[ni][3], hh, ll);
            Ph[(r0 + 8) * PK_STR + ni * 4 + lt] = make_uint2(hh, ll);
        }
        __syncwarp();

#pragma unroll
        for (int ks = 0; ks < 4; ks++) {
            uint2 p0 = Ph[r0 * PK_STR + ks * 8 + lt];
            uint2 p1 = Ph[(r0 + 8) * PK_STR + ks * 8 + lt];
            uint2 p2 = Ph[r0 * PK_STR + ks * 8 + lt + 4];
            uint2 p3 = Ph[(r0 + 8) * PK_STR + ks * 8 + lt + 4];
            uint32_t ph[4] = {p0.x, p1.x, p2.x, p3.x};
            uint32_t pl[4] = {p0.y, p1.y, p2.y, p3.y};
#pragma unroll
            for (int ni = 0; ni < 8; ni++) {
                const int col = ni * 8 + lg;
                uint2 v0 = Vh[(ks * 8 + lt) * FV_STR + col];
                uint2 v1 = Vh[(ks * 8 + lt + 4) * FV_STR + col];
                uint32_t bh[2] = {v0.x, v1.x};
                uint32_t bl[2] = {v0.y, v1.y};
                mma_bf16(oacc[ni], ph, bh);
                mma_bf16(oacc[ni], pl, bh);
                mma_bf16(oacc[ni], ph, bl);
            }
        }
    }

    // ---- epilogue: write attention output as SPLIT PAIRS for gemm_out
    const float inv0 = 1.0f / l0;
    const float inv1 = 1.0f / l1;
    const int grow = qbase + r0;
#pragma unroll
    for (int ni = 0; ni < 8; ni++) {
        uint32_t hh, ll;
        bf_split2(oacc[ni][0] * inv0, oacc[ni][1] * inv0, hh, ll);
        g_atsp[(size_t)(b * SS + grow) * KP + hp + ni * 4 + lt] = make_uint2(hh, ll);
        bf_split2(oacc[ni][2] * inv1, oacc[ni][3] * inv1, hh, ll);
        g_atsp[(size_t)(b * SS + grow + 8) * KP + hp + ni * 4 + lt] = make_uint2(hh, ll);
    }
}

// ---------------- launch ----------------------------------------------------
extern "C" void kernel_launch(void* const* d_in, const int* in_sizes, int n_in,
                              void* d_out, int out_size)
{
    const float* q  = (const float*)d_in[0];
    const float* k  = (const float*)d_in[1];
    const float* v  = (const float*)d_in[2];
    const float* Wq = (const float*)d_in[3];
    const float* bq = (const float*)d_in[4];
    const float* Wk = (const float*)d_in[5];
    const float* bk = (const float*)d_in[6];
    const float* Wv = (const float*)d_in[7];
    const float* bv = (const float*)d_in[8];
    const float* Wo = (const float*)d_in[9];
    const float* bo = (const float*)d_in[10];
    float* out = (float*)d_out;

    cudaFuncSetAttribute(gemm_qkv,
                         cudaFuncAttributeMaxDynamicSharedMemorySize, GEMM4_B);
    cudaFuncSetAttribute(gemm_out,
                         cudaFuncAttributeMaxDynamicSharedMemorySize, GEMM4_B);
    cudaFuncSetAttribute(flash_mma_kernel,
                         cudaFuncAttributeMaxDynamicSharedMemorySize, FLASH6_B);

    dim3 wgrid(512, 1, 4);
    split_w<<<wgrid, 256>>>(Wq, Wk, Wv, Wo);
    dim3 agrid(4096, 1, 3);
    split_act<<<agrid, 256>>>(q, k, v);

    dim3 qkv_grid(EE / 128, MM / 128, 3);
    gemm_qkv<<<qkv_grid, 256, GEMM4_B>>>(bq, bk, bv);

    dim3 fa_grid(SS / 128, HH, BB);
    flash_mma_kernel<<<fa_grid, 256, FLASH6_B>>>();

    dim3 ogrid(EE / 128, MM / 128);
    gemm_out<<<ogrid, 256, GEMM4_B>>>(bo, out);
}